// round 17
// baseline (speedup 1.0000x reference)
#include <cuda_runtime.h>
#include <cuda_fp8.h>
#include <cuda_fp16.h>
#include <cstdint>

// ============================ problem dims ============================
#define MSZ 16384
#define NSZ 2048
#define KSZ 2048

// ============================ GEMM config =============================
#define BM 128
#define BN 128
#define BK 128                // 128 fp8 bytes per row per k-tile (8 k16 groups)
#define KT (KSZ / BK)         // 16 k-tiles
#define STAGES 3
#define ASTRIDE 144           // 128 data + 16 pad: conflict-free LDSM & STS
#define A_SMEM_BYTES (BM * ASTRIDE)   // 18432
#define B_SMEM_BYTES (BN * ASTRIDE)   // 18432
#define STAGE_BYTES (A_SMEM_BYTES + B_SMEM_BYTES)   // 36864
#define SMEM_TOTAL (STAGES * STAGE_BYTES)           // 110592 -> 2 CTAs/SM

// ============================ scratch =================================
// e4m3 bytes, k16-group pair-interleaved: [k0k1 k8k9 k2k3 k10k11 ...]
__device__ __align__(1024) uint8_t g_xq[(size_t)MSZ * KSZ];
__device__ __align__(1024) uint8_t g_wq[(size_t)NSZ * KSZ];
__device__ float g_amax[2];   // zero at load; atomicMax idempotent across replays

// ============================ PTX helpers =============================
__device__ __forceinline__ uint32_t smem_u32(const void* p) {
    uint32_t a;
    asm("{ .reg .u64 t; cvta.to.shared.u64 t, %1; cvt.u32.u64 %0, t; }"
        : "=r"(a) : "l"(p));
    return a;
}

__device__ __forceinline__ void cp_async16(uint32_t dst, const void* src) {
    asm volatile("cp.async.cg.shared.global [%0], [%1], 16;"
                 :: "r"(dst), "l"(src) : "memory");
}
#define CP_COMMIT() asm volatile("cp.async.commit_group;" ::: "memory")
#define CP_WAIT(n)  asm volatile("cp.async.wait_group %0;" :: "n"(n) : "memory")

__device__ __forceinline__ void ldsm_x4(uint32_t* r, uint32_t addr) {
    asm volatile("ldmatrix.sync.aligned.m8n8.x4.shared.b16 {%0,%1,%2,%3}, [%4];"
                 : "=r"(r[0]), "=r"(r[1]), "=r"(r[2]), "=r"(r[3])
                 : "r"(addr));
}

// packed e4m3x2 (low 16 bits) -> f16x2, exact
__device__ __forceinline__ uint32_t cvt2(uint32_t x) {
    __half2_raw h = __nv_cvt_fp8x2_to_halfraw2((__nv_fp8x2_storage_t)x, __NV_E4M3);
    return *(uint32_t*)&h;
}

__device__ __forceinline__ void mma_f16(float d[4], const uint32_t a[4],
                                        const uint32_t b[2]) {
    asm volatile(
        "mma.sync.aligned.m16n8k16.row.col.f32.f16.f16.f32 "
        "{%0,%1,%2,%3}, {%4,%5,%6,%7}, {%8,%9}, {%0,%1,%2,%3};"
        : "+f"(d[0]), "+f"(d[1]), "+f"(d[2]), "+f"(d[3])
        : "r"(a[0]), "r"(a[1]), "r"(a[2]), "r"(a[3]),
          "r"(b[0]), "r"(b[1]));
}

// quantize float2 -> packed e4m3x2 (uint16)
__device__ __forceinline__ uint32_t qpair(float a, float b) {
    return (uint32_t)__nv_cvt_float2_to_fp8x2(make_float2(a, b),
                                              __NV_SATFINITE, __NV_E4M3);
}

// ============================ quant kernels ===========================

// x [M,K] f32 -> g_xq [M,K] e4m3 (scaled, k16-interleaved); amax -> g_amax[0]
__global__ void quant_x_kernel(const float* __restrict__ x,
                               const float* __restrict__ scale) {
    const float s = __ldg(&scale[0]);
    const int ngrp = (MSZ * KSZ) / 16;
    const int stride = gridDim.x * blockDim.x;
    float amax = 0.0f;
    for (int g = blockIdx.x * blockDim.x + threadIdx.x; g < ngrp; g += stride) {
        const float4* xg = (const float4*)(x + (size_t)g * 16);
        float4 v0 = xg[0], v1 = xg[1], v2 = xg[2], v3 = xg[3];
        amax = fmaxf(amax, fmaxf(
            fmaxf(fmaxf(fabsf(v0.x), fabsf(v0.y)), fmaxf(fabsf(v0.z), fabsf(v0.w))),
            fmaxf(fmaxf(fabsf(v1.x), fabsf(v1.y)), fmaxf(fabsf(v1.z), fabsf(v1.w)))));
        amax = fmaxf(amax, fmaxf(
            fmaxf(fmaxf(fabsf(v2.x), fabsf(v2.y)), fmaxf(fabsf(v2.z), fabsf(v2.w))),
            fmaxf(fmaxf(fabsf(v3.x), fabsf(v3.y)), fmaxf(fabsf(v3.z), fabsf(v3.w)))));
        uint32_t p0 = qpair(v0.x * s, v0.y * s);
        uint32_t p1 = qpair(v0.z * s, v0.w * s);
        uint32_t p2 = qpair(v1.x * s, v1.y * s);
        uint32_t p3 = qpair(v1.z * s, v1.w * s);
        uint32_t p4 = qpair(v2.x * s, v2.y * s);
        uint32_t p5 = qpair(v2.z * s, v2.w * s);
        uint32_t p6 = qpair(v3.x * s, v3.y * s);
        uint32_t p7 = qpair(v3.z * s, v3.w * s);
        uint4 o;
        o.x = p0 | (p4 << 16);
        o.y = p1 | (p5 << 16);
        o.z = p2 | (p6 << 16);
        o.w = p3 | (p7 << 16);
        *(uint4*)(g_xq + (size_t)g * 16) = o;
    }
    #pragma unroll
    for (int o = 16; o; o >>= 1)
        amax = fmaxf(amax, __shfl_xor_sync(0xFFFFFFFFu, amax, o));
    __shared__ float wmax[8];
    if ((threadIdx.x & 31) == 0) wmax[threadIdx.x >> 5] = amax;
    __syncthreads();
    if (threadIdx.x == 0) {
        float m = wmax[0];
        #pragma unroll
        for (int i = 1; i < 8; i++) m = fmaxf(m, wmax[i]);
        atomicMax((int*)&g_amax[0], __float_as_int(m));
    }
}

// kernel [K,N] f32 -> g_wq [N,K] e4m3 (transpose, scaled, k16-interleaved)
__global__ void quant_w_kernel(const float* __restrict__ w,
                               const float* __restrict__ scale) {
    __shared__ float tile[32][33];
    const float s = __ldg(&scale[1]);
    const int k0 = blockIdx.y * 32, n0 = blockIdx.x * 32;
    const int tx = threadIdx.x, ty = threadIdx.y;   // block (8, 32)
    const int t = ty * 8 + tx;                      // 0..255
    float amax = 0.0f;
    #pragma unroll
    for (int it = 0; it < 4; it++) {
        int e = it * 256 + t;
        int kk = e >> 5, nn = e & 31;
        float v = w[(size_t)(k0 + kk) * NSZ + n0 + nn];
        amax = fmaxf(amax, fabsf(v));
        tile[kk][nn] = v;
    }
    __syncthreads();
    if (t < 64) {
        const int n = t >> 1, kb = (t & 1) * 16;
        uint32_t p[8];
        #pragma unroll
        for (int j = 0; j < 8; j++)
            p[j] = qpair(tile[kb + 2 * j][n] * s, tile[kb + 2 * j + 1][n] * s);
        uint4 o;
        o.x = p[0] | (p[4] << 16);
        o.y = p[1] | (p[5] << 16);
        o.z = p[2] | (p[6] << 16);
        o.w = p[3] | (p[7] << 16);
        *(uint4*)(g_wq + (size_t)(n0 + n) * KSZ + k0 + kb) = o;
    }

    #pragma unroll
    for (int of = 16; of; of >>= 1)
        amax = fmaxf(amax, __shfl_xor_sync(0xFFFFFFFFu, amax, of));
    __shared__ float wmax[8];
    if ((t & 31) == 0) wmax[t >> 5] = amax;
    __syncthreads();
    if (t == 0) {
        float m = wmax[0];
        #pragma unroll
        for (int i = 1; i < 8; i++) m = fmaxf(m, wmax[i]);
        atomicMax((int*)&g_amax[1], __float_as_int(m));
    }
}

// faithful _sf_compute + rolled history (all zeros for H=1)
__global__ void scale_update_kernel(const float* __restrict__ scale,
                                    float* __restrict__ tail) {
    int i = threadIdx.x;
    if (i < 2) {
        float a = g_amax[i];
        float s = __ldg(&scale[i]);
        float e = floorf(log2f(448.0f / a));
        float sf = rintf(exp2f(fabsf(e)));
        sf = (a > 0.0f) ? sf : s;
        sf = isinf(a) ? sf : s;
        sf = (e < 0.0f) ? (1.0f / sf) : sf;
        tail[i] = sf;          // new_scale
        tail[2 + i] = 0.0f;    // rolled amax_history
    }
}

// ================= GEMM: fp8 smem -> cvt once -> fp16 HMMA ===========
// C[m0:+128, n0:+128] = A @ B^T. 256 threads, 8 warps (2x4), warp tile
// 64x32. BK=128 (8 k16 steps/tile, 16 iters). 3-stage cp.async ring.
// 2 CTAs/SM: one CTA's HMMA stream covers the other's pipeline bubbles.
__global__ void __launch_bounds__(256, 2) gemm_kernel(
    float* __restrict__ out, const float* __restrict__ scale)
{
    extern __shared__ char smem[];
    const uint32_t sb = smem_u32(smem);
    const int tid = threadIdx.x, wid = tid >> 5, lane = tid & 31;
    const int m0 = blockIdx.y * BM, n0 = blockIdx.x * BN;
    const int wm = (wid >> 2) * 64, wn = (wid & 3) * 32;

    // LDSM row = lane
    const uint32_t a_base = sb + (wm + lane) * ASTRIDE;
    const uint32_t b_base = sb + A_SMEM_BYTES + (wn + lane) * ASTRIDE;

    // cp.async: row = tid>>1 (0..127), col = (tid&1)*64, 4x16B chunks.
    // phase-octet banks: r*9 + {0,4} + c mod 32 distinct -> conflict-free.
    const int ldrow = tid >> 1;
    const int ldcol = (tid & 1) * 64;
    const uint8_t* ag = g_xq + (size_t)(m0 + ldrow) * KSZ + ldcol;
    const uint8_t* bg = g_wq + (size_t)(n0 + ldrow) * KSZ + ldcol;
    const uint32_t adst = sb + ldrow * ASTRIDE + ldcol;
    const uint32_t bdst = sb + A_SMEM_BYTES + ldrow * ASTRIDE + ldcol;

    float acc[4][4][4] = {};

    // ---- prologue: fill 2 of 3 stages ----
    #pragma unroll
    for (int s = 0; s < STAGES - 1; s++) {
        const uint32_t so = s * STAGE_BYTES;
        const int k0 = s * BK;
        #pragma unroll
        for (int c = 0; c < 4; c++) {
            cp_async16(adst + so + c * 16, ag + k0 + c * 16);
            cp_async16(bdst + so + c * 16, bg + k0 + c * 16);
        }
        CP_COMMIT();
    }

    uint32_t so = 0;
    uint32_t no = (STAGES - 1) * STAGE_BYTES;
    for (int it = 0; it < KT; it++) {
        CP_WAIT(STAGES - 2);
        __syncthreads();

        const int nxt = it + STAGES - 1;
        if (nxt < KT) {
            const int k0 = nxt * BK;
            #pragma unroll
            for (int c = 0; c < 4; c++) {
                cp_async16(adst + no + c * 16, ag + k0 + c * 16);
                cp_async16(bdst + no + c * 16, bg + k0 + c * 16);
            }
        }
        CP_COMMIT();
        no += STAGE_BYTES; if (no == SMEM_TOTAL) no = 0;

        // ---- 8 ksteps, raw fragments double-buffered ----
        // raw[buf][0..3]=A rows wm..wm+31, [4..7]=A rows wm+32..63, [8..11]=B
        uint32_t raw[2][12];
        ldsm_x4(&raw[0][0], a_base + so);
        ldsm_x4(&raw[0][4], a_base + so + 32 * ASTRIDE);
        ldsm_x4(&raw[0][8], b_base + so);
        #pragma unroll
        for (int ks = 0; ks < 8; ks++) {
            const int cur = ks & 1, nxtb = cur ^ 1;
            if (ks < 7) {
                const uint32_t kb = so + (ks + 1) * 16;
                ldsm_x4(&raw[nxtb][0], a_base + kb);
                ldsm_x4(&raw[nxtb][4], a_base + kb + 32 * ASTRIDE);
                ldsm_x4(&raw[nxtb][8], b_base + kb);
            }
            uint32_t B[4][2];
            #pragma unroll
            for (int nt = 0; nt < 4; nt++) {
                B[nt][0] = cvt2(raw[cur][8 + nt] & 0xFFFFu);
                B[nt][1] = cvt2(raw[cur][8 + nt] >> 16);
            }
            #pragma unroll
            for (int mt = 0; mt < 4; mt++) {
                uint32_t A[4];
                A[0] = cvt2(raw[cur][2 * mt] & 0xFFFFu);
                A[2] = cvt2(raw[cur][2 * mt] >> 16);
                A[1] = cvt2(raw[cur][2 * mt + 1] & 0xFFFFu);
                A[3] = cvt2(raw[cur][2 * mt + 1] >> 16);
                #pragma unroll
                for (int nt = 0; nt < 4; nt++)
                    mma_f16(acc[mt][nt], A, B[nt]);
            }
        }

        so += STAGE_BYTES; if (so == SMEM_TOTAL) so = 0;
    }

    // ---- epilogue ----
    const float inv = (1.0f / __ldg(&scale[0])) * (1.0f / __ldg(&scale[1]));
    const int lrow = lane >> 2;
    #pragma unroll
    for (int mt = 0; mt < 4; mt++) {
        const int row = m0 + wm + mt * 16 + lrow;
        #pragma unroll
        for (int nt = 0; nt < 4; nt++) {
            const int col = n0 + wn + nt * 8 + (lane & 3) * 2;
            float2 v0 = make_float2(acc[mt][nt][0] * inv, acc[mt][nt][1] * inv);
            float2 v1 = make_float2(acc[mt][nt][2] * inv, acc[mt][nt][3] * inv);
            *(float2*)&out[(size_t)row * NSZ + col] = v0;
            *(float2*)&out[(size_t)(row + 8) * NSZ + col] = v1;
        }
    }
}

// ============================ host launch =============================
extern "C" void kernel_launch(void* const* d_in, const int* in_sizes, int n_in,
                              void* d_out, int out_size) {
    const float* x     = (const float*)d_in[0];
    const float* w     = (const float*)d_in[1];
    const float* scale = (const float*)d_in[2];
    float* out = (float*)d_out;

    // launch order keeps the GEMM at sampled index 3 for ncu
    quant_x_kernel<<<1184, 256>>>(x, scale);                                   // 0
    quant_w_kernel<<<dim3(NSZ / 32, KSZ / 32), dim3(8, 32)>>>(w, scale);       // 1
    scale_update_kernel<<<1, 32>>>(scale, out + (out_size - 4));               // 2

    static bool attr_set = false;
    if (!attr_set) {
        cudaFuncSetAttribute(gemm_kernel,
                             cudaFuncAttributeMaxDynamicSharedMemorySize,
                             SMEM_TOTAL);
        attr_set = true;
    }
    gemm_kernel<<<dim3(NSZ / BN, MSZ / BM), 256, SMEM_TOTAL>>>(out, scale);    // 3
}